// round 16
// baseline (speedup 1.0000x reference)
#include <cuda_runtime.h>
#include <cuda_bf16.h>

// Problem constants
#define BB 16
#define TT 24
#define NN 2048
#define FF 64
#define BT (BB*TT)          // 384
#define NF (NN*FF)          // 131072
#define NF4 (NF/4)          // 32768 float4 per (b,t) row
#define NOCT 8

// Scratch (device globals; no allocation allowed). All fully overwritten each call.
__device__ float d_lfp[NOCT*BT*FF];    // lhs_f partials (8 octants per bt)
__device__ float d_Gp [NOCT*BT*FF];    // G partials (8 octants per bt)
__device__ float d_A  [BB*TT*TT];      // attention weights

// Streaming store (evict-first): out is never re-read, keep it from evicting x.
__device__ __forceinline__ void stcs4(float4* p, float4 v) {
    asm volatile("st.global.cs.v4.f32 [%0], {%1,%2,%3,%4};"
                 :: "l"(p), "f"(v.x), "f"(v.y), "f"(v.z), "f"(v.w) : "memory");
}

// ---------------------------------------------------------------------------
// Kernel 1: single pass over ALL of x; k2's GEMM fused as a TAIL phase.
// Each CTA (128 thr) handles one octant (256 rows) of one (b,t).
// grid = BT*8 = 3072 CTAs.
// Main loop (unchanged, fully unrolled, MLP ~32):
//   d[n]   = sum_f x[n,f]*U3[f]   -> smem (NOT global)
//   acc[f] += x[n,f]*U1[n]        -> lfp partial
// Tail (after the x stream, per CTA):
//   Gp_oct[f] = sum_{i<256} d[i] * U2[oct*256+i, f]   (U2 slice L2-resident)
// ---------------------------------------------------------------------------
__global__ __launch_bounds__(128) void k1_pass(
    const float* __restrict__ x, const float* __restrict__ U1,
    const float* __restrict__ U2, const float* __restrict__ U3,
    float* __restrict__ lfp, float* __restrict__ Gp)
{
    const int bt   = blockIdx.x >> 3;
    const int oct  = blockIdx.x & 7;
    const int w    = threadIdx.x >> 5;
    const int lane = threadIdx.x & 31;
    const int r    = lane >> 2;
    const int q    = lane & 3;
    const float4* xb = (const float4*)(x + (size_t)bt * NF);

    __shared__ float sds[256];       // row dots d[n] for this octant
    __shared__ float sred[4][FF];    // lfp cross-warp reduce
    __shared__ float sredG[2][FF];   // tail half-sums

    float4 u3[4];
    #pragma unroll
    for (int j = 0; j < 4; j++) u3[j] = ((const float4*)U3)[q + 4*j];

    const int n0 = oct * 256 + w * 64;

    // preload the 8 U1 values this lane's rows need (independent LDG.32)
    float u1v[8];
    #pragma unroll
    for (int k = 0; k < 8; k++) u1v[k] = __ldg(U1 + n0 + 8*k + r);

    float4 acc[4];
    #pragma unroll
    for (int j = 0; j < 4; j++) acc[j] = make_float4(0.f,0.f,0.f,0.f);

    #pragma unroll
    for (int k = 0; k < 8; k++) {
        const int n = n0 + 8*k + r;
        const float4* row = xb + (size_t)n * 16;
        const float u1 = u1v[k];
        float d = 0.f;
        #pragma unroll
        for (int j = 0; j < 4; j++) {
            float4 v = row[q + 4*j];
            d += v.x*u3[j].x + v.y*u3[j].y + v.z*u3[j].z + v.w*u3[j].w;
            acc[j].x += v.x*u1; acc[j].y += v.y*u1;
            acc[j].z += v.z*u1; acc[j].w += v.w*u1;
        }
        d += __shfl_down_sync(0xffffffffu, d, 2, 4);
        d += __shfl_down_sync(0xffffffffu, d, 1, 4);
        if (q == 0) sds[w*64 + 8*k + r] = d;
    }

    #pragma unroll
    for (int off = 16; off >= 4; off >>= 1) {
        #pragma unroll
        for (int j = 0; j < 4; j++) {
            acc[j].x += __shfl_down_sync(0xffffffffu, acc[j].x, off);
            acc[j].y += __shfl_down_sync(0xffffffffu, acc[j].y, off);
            acc[j].z += __shfl_down_sync(0xffffffffu, acc[j].z, off);
            acc[j].w += __shfl_down_sync(0xffffffffu, acc[j].w, off);
        }
    }

    if (lane < 4) {
        #pragma unroll
        for (int j = 0; j < 4; j++)
            ((float4*)sred[w])[q + 4*j] = acc[j];
    }
    __syncthreads();

    // lfp partial write (64 threads)
    if (threadIdx.x < FF) {
        float t = 0.f;
        #pragma unroll
        for (int p = 0; p < 4; p++) t += sred[p][threadIdx.x];
        lfp[(bt*NOCT + oct)*FF + threadIdx.x] = t;
    }

    // ---- tail: G partial for this octant (128 threads: half h, col f) ----
    {
        const int h = threadIdx.x >> 6;          // 0 or 1
        const int f = threadIdx.x & 63;
        const float* u2b = U2 + (size_t)(oct*256 + h*128) * FF + f;
        float g0 = 0.f, g1 = 0.f, g2 = 0.f, g3 = 0.f;
        #pragma unroll 8
        for (int i = 0; i < 128; i += 4) {
            g0 += sds[h*128 + i    ] * __ldg(u2b + (size_t)(i    )*FF);
            g1 += sds[h*128 + i + 1] * __ldg(u2b + (size_t)(i + 1)*FF);
            g2 += sds[h*128 + i + 2] * __ldg(u2b + (size_t)(i + 2)*FF);
            g3 += sds[h*128 + i + 3] * __ldg(u2b + (size_t)(i + 3)*FF);
        }
        sredG[h][f] = (g0 + g1) + (g2 + g3);
    }
    __syncthreads();
    if (threadIdx.x < FF)
        Gp[(bt*NOCT + oct)*FF + threadIdx.x] =
            sredG[0][threadIdx.x] + sredG[1][threadIdx.x];
}

// ---------------------------------------------------------------------------
// Kernel 3: per batch: product -> sigmoid(+be) -> E -> softmax.
// lfp and Gp each summed over 8 octant partials.
// ---------------------------------------------------------------------------
__global__ __launch_bounds__(576) void k3_scores(
    const float* __restrict__ lfp, const float* __restrict__ Gp,
    const float* __restrict__ be, const float* __restrict__ Ve,
    float* __restrict__ A)
{
    const int b = blockIdx.x;
    __shared__ float lfs[TT*65], Gs[TT*65], sg[TT*25], Em[TT*25];
    __shared__ float cmax[TT], csum[TT];
    const int tid = threadIdx.x;

    for (int e = tid; e < TT*FF; e += 576) {
        int t = e >> 6, f = e & 63;
        const int bt = b*TT + t;
        float lv = 0.f, gv = 0.f;
        #pragma unroll
        for (int p = 0; p < NOCT; p++) {
            lv += lfp[(bt*NOCT + p)*FF + f];
            gv += Gp [(bt*NOCT + p)*FF + f];
        }
        lfs[t*65 + f] = lv;
        Gs [t*65 + f] = gv;
    }
    __syncthreads();

    const int t = tid / TT;
    const int s = tid % TT;
    float p = 0.f;
    #pragma unroll
    for (int f = 0; f < FF; f++)
        p += lfs[t*65 + f] * Gs[s*65 + f];
    sg[t*25 + s] = 1.f / (1.f + __expf(-(p + be[t*TT + s])));
    __syncthreads();

    float e = 0.f;
    #pragma unroll
    for (int s2 = 0; s2 < TT; s2++)
        e += Ve[t*TT + s2] * sg[s2*25 + s];
    Em[t*25 + s] = e;
    __syncthreads();

    if (t == 0) {
        float m = -1e30f;
        #pragma unroll
        for (int tt2 = 0; tt2 < TT; tt2++) m = fmaxf(m, Em[tt2*25 + s]);
        cmax[s] = m;
    }
    __syncthreads();
    const float ex = __expf(Em[t*25 + s] - cmax[s]);
    Em[t*25 + s] = ex;
    __syncthreads();
    if (t == 0) {
        float sm = 0.f;
        #pragma unroll
        for (int tt2 = 0; tt2 < TT; tt2++) sm += Em[tt2*25 + s];
        csum[s] = sm;
    }
    __syncthreads();
    A[b*TT*TT + t*TT + s] = ex / csum[s];
}

// ---------------------------------------------------------------------------
// Kernel 4 (FROZEN at R13 best): out[b,s,nf] = sum_t x[b,t,nf] * A[b,t,s].
// float4 column per thread (xr = 24 x float4), s in pairs, A as float2 in
// smem, 4 CTAs/SM, reverse batch order, .cs streaming stores.
// ---------------------------------------------------------------------------
__global__ __launch_bounds__(128, 4) void k4_out(
    const float4* __restrict__ x4, const float* __restrict__ A,
    float4* __restrict__ out4)
{
    __shared__ float2 As2[TT*12];
    const int b = (BB - 1) - blockIdx.y;
    const float2* Ab2 = (const float2*)(A + b*TT*TT);
    for (int i = threadIdx.x; i < TT*12; i += 128)
        As2[i] = Ab2[i];
    __syncthreads();

    const size_t c = (size_t)blockIdx.x * 128 + threadIdx.x;
    const float4* xb = x4 + (size_t)b * TT * NF4 + c;

    float4 xr[TT];
    #pragma unroll
    for (int t = 0; t < TT; t++) xr[t] = xb[(size_t)t * NF4];

    float4* ob = out4 + (size_t)b * TT * NF4 + c;
    #pragma unroll 1
    for (int sp = 0; sp < 12; sp++) {
        float4 a0 = make_float4(0.f,0.f,0.f,0.f);
        float4 a1 = make_float4(0.f,0.f,0.f,0.f);
        #pragma unroll
        for (int t = 0; t < TT; t++) {
            const float2 av = As2[t*12 + sp];
            a0.x += xr[t].x*av.x; a0.y += xr[t].y*av.x; a0.z += xr[t].z*av.x; a0.w += xr[t].w*av.x;
            a1.x += xr[t].x*av.y; a1.y += xr[t].y*av.y; a1.z += xr[t].z*av.y; a1.w += xr[t].w*av.y;
        }
        stcs4(ob + (size_t)(2*sp    ) * NF4, a0);
        stcs4(ob + (size_t)(2*sp + 1) * NF4, a1);
    }
}

// ---------------------------------------------------------------------------
extern "C" void kernel_launch(void* const* d_in, const int* in_sizes, int n_in,
                              void* d_out, int out_size)
{
    const float* x  = (const float*)d_in[0];
    const float* U1 = (const float*)d_in[1];
    const float* U2 = (const float*)d_in[2];
    const float* U3 = (const float*)d_in[3];
    const float* be = (const float*)d_in[4];
    const float* Ve = (const float*)d_in[5];

    float *lfp, *Gp, *A;
    cudaGetSymbolAddress((void**)&lfp, d_lfp);
    cudaGetSymbolAddress((void**)&Gp,  d_Gp);
    cudaGetSymbolAddress((void**)&A,   d_A);

    k1_pass<<<BT*NOCT, 128>>>(x, U1, U2, U3, lfp, Gp);
    k3_scores<<<BB, 576>>>(lfp, Gp, be, Ve, A);
    k4_out<<<dim3(NF4/128, BB), 128>>>((const float4*)x, A, (float4*)d_out);
}

// round 17
// speedup vs baseline: 1.0143x; 1.0143x over previous
#include <cuda_runtime.h>
#include <cuda_bf16.h>

// Problem constants
#define BB 16
#define TT 24
#define NN 2048
#define FF 64
#define BT (BB*TT)          // 384
#define NF (NN*FF)          // 131072
#define NF4 (NF/4)          // 32768 float4 per (b,t) row
#define NOCT 8

// Scratch (device globals; no allocation allowed). All fully overwritten each call.
__device__ float d_lfp[NOCT*BT*FF];    // lhs_f partials (8 octants per bt)
__device__ float d_Gp [NOCT*BT*FF];    // G partials (8 octants per bt)
__device__ float d_A  [BB*TT*TT];      // attention weights

// Streaming store (evict-first): out is never re-read, keep it from evicting x.
__device__ __forceinline__ void stcs4(float4* p, float4 v) {
    asm volatile("st.global.cs.v4.f32 [%0], {%1,%2,%3,%4};"
                 :: "l"(p), "f"(v.x), "f"(v.y), "f"(v.z), "f"(v.w) : "memory");
}

// ---------------------------------------------------------------------------
// Kernel 1: single pass over ALL of x; k2's GEMM fused as a TAIL phase.
// Each CTA (128 thr) handles one octant (256 rows) of one (b,t).
// grid = BT*8 = 3072 CTAs.
// Main loop (fully unrolled, MLP ~32):
//   d[n]   = sum_f x[n,f]*U3[f]   -> smem
//   acc[f] += x[n,f]*U1[n]        -> lfp partial
// Tail (vectorized): thread (rg = tid>>4 owns 32 rows, f4 = tid&15 owns 4
// cols). Per iter: 1 broadcast LDS + 1 LDG.128 (U2, L2-resident) + 4 FMA.
//   Gp_oct[f] = sum_{i<256} d[i] * U2[oct*256+i, f]
// ---------------------------------------------------------------------------
__global__ __launch_bounds__(128) void k1_pass(
    const float* __restrict__ x, const float* __restrict__ U1,
    const float* __restrict__ U2, const float* __restrict__ U3,
    float* __restrict__ lfp, float* __restrict__ Gp)
{
    const int bt   = blockIdx.x >> 3;
    const int oct  = blockIdx.x & 7;
    const int w    = threadIdx.x >> 5;
    const int lane = threadIdx.x & 31;
    const int r    = lane >> 2;
    const int q    = lane & 3;
    const float4* xb = (const float4*)(x + (size_t)bt * NF);

    __shared__ float  sds[256];       // row dots d[i] for this octant
    __shared__ float  sred[4][FF];    // lfp cross-warp reduce
    __shared__ float4 sG[8][16];      // tail row-group partials

    float4 u3[4];
    #pragma unroll
    for (int j = 0; j < 4; j++) u3[j] = ((const float4*)U3)[q + 4*j];

    const int n0 = oct * 256 + w * 64;

    // preload the 8 U1 values this lane's rows need (independent LDG.32)
    float u1v[8];
    #pragma unroll
    for (int k = 0; k < 8; k++) u1v[k] = __ldg(U1 + n0 + 8*k + r);

    float4 acc[4];
    #pragma unroll
    for (int j = 0; j < 4; j++) acc[j] = make_float4(0.f,0.f,0.f,0.f);

    #pragma unroll
    for (int k = 0; k < 8; k++) {
        const int n = n0 + 8*k + r;
        const float4* row = xb + (size_t)n * 16;
        const float u1 = u1v[k];
        float d = 0.f;
        #pragma unroll
        for (int j = 0; j < 4; j++) {
            float4 v = row[q + 4*j];
            d += v.x*u3[j].x + v.y*u3[j].y + v.z*u3[j].z + v.w*u3[j].w;
            acc[j].x += v.x*u1; acc[j].y += v.y*u1;
            acc[j].z += v.z*u1; acc[j].w += v.w*u1;
        }
        d += __shfl_down_sync(0xffffffffu, d, 2, 4);
        d += __shfl_down_sync(0xffffffffu, d, 1, 4);
        if (q == 0) sds[w*64 + 8*k + r] = d;
    }

    #pragma unroll
    for (int off = 16; off >= 4; off >>= 1) {
        #pragma unroll
        for (int j = 0; j < 4; j++) {
            acc[j].x += __shfl_down_sync(0xffffffffu, acc[j].x, off);
            acc[j].y += __shfl_down_sync(0xffffffffu, acc[j].y, off);
            acc[j].z += __shfl_down_sync(0xffffffffu, acc[j].z, off);
            acc[j].w += __shfl_down_sync(0xffffffffu, acc[j].w, off);
        }
    }

    if (lane < 4) {
        #pragma unroll
        for (int j = 0; j < 4; j++)
            ((float4*)sred[w])[q + 4*j] = acc[j];
    }
    __syncthreads();

    // lfp partial write (64 threads)
    if (threadIdx.x < FF) {
        float t = 0.f;
        #pragma unroll
        for (int p = 0; p < 4; p++) t += sred[p][threadIdx.x];
        lfp[(bt*NOCT + oct)*FF + threadIdx.x] = t;
    }

    // ---- tail: G partial for this octant, vectorized ----
    {
        const int f4 = threadIdx.x & 15;   // 4 cols: f = f4*4
        const int rg = threadIdx.x >> 4;   // 8 groups of 32 rows
        const float4* u2b =
            (const float4*)(U2 + (size_t)(oct*256 + rg*32) * FF) + f4;
        float4 g = make_float4(0.f,0.f,0.f,0.f);
        #pragma unroll 8
        for (int i = 0; i < 32; i++) {
            const float dv = sds[rg*32 + i];
            const float4 u = __ldg(u2b + (size_t)i * (FF/4));
            g.x += dv*u.x; g.y += dv*u.y; g.z += dv*u.z; g.w += dv*u.w;
        }
        sG[rg][f4] = g;
    }
    __syncthreads();
    if (threadIdx.x < 16) {
        float4 s = sG[0][threadIdx.x];
        #pragma unroll
        for (int p = 1; p < 8; p++) {
            const float4 v = sG[p][threadIdx.x];
            s.x += v.x; s.y += v.y; s.z += v.z; s.w += v.w;
        }
        *(float4*)&Gp[(bt*NOCT + oct)*FF + threadIdx.x*4] = s;
    }
}

// ---------------------------------------------------------------------------
// Kernel 3: per batch: product -> sigmoid(+be) -> E -> softmax.
// lfp and Gp each summed over 8 octant partials.
// ---------------------------------------------------------------------------
__global__ __launch_bounds__(576) void k3_scores(
    const float* __restrict__ lfp, const float* __restrict__ Gp,
    const float* __restrict__ be, const float* __restrict__ Ve,
    float* __restrict__ A)
{
    const int b = blockIdx.x;
    __shared__ float lfs[TT*65], Gs[TT*65], sg[TT*25], Em[TT*25];
    __shared__ float cmax[TT], csum[TT];
    const int tid = threadIdx.x;

    for (int e = tid; e < TT*FF; e += 576) {
        int t = e >> 6, f = e & 63;
        const int bt = b*TT + t;
        float lv = 0.f, gv = 0.f;
        #pragma unroll
        for (int p = 0; p < NOCT; p++) {
            lv += lfp[(bt*NOCT + p)*FF + f];
            gv += Gp [(bt*NOCT + p)*FF + f];
        }
        lfs[t*65 + f] = lv;
        Gs [t*65 + f] = gv;
    }
    __syncthreads();

    const int t = tid / TT;
    const int s = tid % TT;
    float p = 0.f;
    #pragma unroll
    for (int f = 0; f < FF; f++)
        p += lfs[t*65 + f] * Gs[s*65 + f];
    sg[t*25 + s] = 1.f / (1.f + __expf(-(p + be[t*TT + s])));
    __syncthreads();

    float e = 0.f;
    #pragma unroll
    for (int s2 = 0; s2 < TT; s2++)
        e += Ve[t*TT + s2] * sg[s2*25 + s];
    Em[t*25 + s] = e;
    __syncthreads();

    if (t == 0) {
        float m = -1e30f;
        #pragma unroll
        for (int tt2 = 0; tt2 < TT; tt2++) m = fmaxf(m, Em[tt2*25 + s]);
        cmax[s] = m;
    }
    __syncthreads();
    const float ex = __expf(Em[t*25 + s] - cmax[s]);
    Em[t*25 + s] = ex;
    __syncthreads();
    if (t == 0) {
        float sm = 0.f;
        #pragma unroll
        for (int tt2 = 0; tt2 < TT; tt2++) sm += Em[tt2*25 + s];
        csum[s] = sm;
    }
    __syncthreads();
    A[b*TT*TT + t*TT + s] = ex / csum[s];
}

// ---------------------------------------------------------------------------
// Kernel 4 (FROZEN at R13 best): out[b,s,nf] = sum_t x[b,t,nf] * A[b,t,s].
// float4 column per thread (xr = 24 x float4), s in pairs, A as float2 in
// smem, 4 CTAs/SM, reverse batch order, .cs streaming stores.
// ---------------------------------------------------------------------------
__global__ __launch_bounds__(128, 4) void k4_out(
    const float4* __restrict__ x4, const float* __restrict__ A,
    float4* __restrict__ out4)
{
    __shared__ float2 As2[TT*12];
    const int b = (BB - 1) - blockIdx.y;
    const float2* Ab2 = (const float2*)(A + b*TT*TT);
    for (int i = threadIdx.x; i < TT*12; i += 128)
        As2[i] = Ab2[i];
    __syncthreads();

    const size_t c = (size_t)blockIdx.x * 128 + threadIdx.x;
    const float4* xb = x4 + (size_t)b * TT * NF4 + c;

    float4 xr[TT];
    #pragma unroll
    for (int t = 0; t < TT; t++) xr[t] = xb[(size_t)t * NF4];

    float4* ob = out4 + (size_t)b * TT * NF4 + c;
    #pragma unroll 1
    for (int sp = 0; sp < 12; sp++) {
        float4 a0 = make_float4(0.f,0.f,0.f,0.f);
        float4 a1 = make_float4(0.f,0.f,0.f,0.f);
        #pragma unroll
        for (int t = 0; t < TT; t++) {
            const float2 av = As2[t*12 + sp];
            a0.x += xr[t].x*av.x; a0.y += xr[t].y*av.x; a0.z += xr[t].z*av.x; a0.w += xr[t].w*av.x;
            a1.x += xr[t].x*av.y; a1.y += xr[t].y*av.y; a1.z += xr[t].z*av.y; a1.w += xr[t].w*av.y;
        }
        stcs4(ob + (size_t)(2*sp    ) * NF4, a0);
        stcs4(ob + (size_t)(2*sp + 1) * NF4, a1);
    }
}

// ---------------------------------------------------------------------------
extern "C" void kernel_launch(void* const* d_in, const int* in_sizes, int n_in,
                              void* d_out, int out_size)
{
    const float* x  = (const float*)d_in[0];
    const float* U1 = (const float*)d_in[1];
    const float* U2 = (const float*)d_in[2];
    const float* U3 = (const float*)d_in[3];
    const float* be = (const float*)d_in[4];
    const float* Ve = (const float*)d_in[5];

    float *lfp, *Gp, *A;
    cudaGetSymbolAddress((void**)&lfp, d_lfp);
    cudaGetSymbolAddress((void**)&Gp,  d_Gp);
    cudaGetSymbolAddress((void**)&A,   d_A);

    k1_pass<<<BT*NOCT, 128>>>(x, U1, U2, U3, lfp, Gp);
    k3_scores<<<BB, 576>>>(lfp, Gp, be, Ve, A);
    k4_out<<<dim3(NF4/128, BB), 128>>>((const float4*)x, A, (float4*)d_out);
}